// round 2
// baseline (speedup 1.0000x reference)
#include <cuda_runtime.h>
#include <math_constants.h>
#include <cstdint>

#define MROWS 200
#define NCOLS 6
#define TOT   1200   // MROWS*NCOLS
#define KSEL  25
#define DIN   784
#define BMAX  16384

// ---------------- device scratch (static; no runtime allocation) ----------------
__device__ float g_WbT[TOT * TOT];          // Wb transposed: column c of Wb = row c of WbT
__device__ float g_ZA[BMAX * MROWS];        // precomputed Wa@x_t + ba
__device__ float g_Ymax[BMAX * MROWS];      // recorded y.max(axis=1) per step

// ---------------- transpose Wb -> g_WbT ----------------
__global__ void transpose_wb(const float* __restrict__ Wb) {
    __shared__ float tile[32][33];
    int bx = blockIdx.x * 32, by = blockIdx.y * 32;
    int x = bx + threadIdx.x;   // column of Wb
    if (x < TOT) {
        for (int dy = 0; dy < 32; dy += 8) {
            int yy = by + threadIdx.y + dy;      // row of Wb
            if (yy < TOT) tile[threadIdx.y + dy][threadIdx.x] = Wb[(size_t)yy * TOT + x];
        }
    }
    __syncthreads();
    int r = by + threadIdx.x;   // row of Wb = column index inside WbT row
    if (r < TOT) {
        for (int dy = 0; dy < 32; dy += 8) {
            int c = bx + threadIdx.y + dy;       // column of Wb = row of WbT
            if (c < TOT) g_WbT[(size_t)c * TOT + r] = tile[threadIdx.x][threadIdx.y + dy];
        }
    }
}

// ---------------- generic C[M,N] = A[M,K] @ B[N,K]^T + bias[N] ----------------
__global__ void gemm_abt_kernel(const float* __restrict__ A, const float* __restrict__ Bw,
                                const float* __restrict__ bias, float* __restrict__ C,
                                int Mdim, int Ndim, int Kdim)
{
    const int TK = 16;
    __shared__ float As[TK][64 + 4];
    __shared__ float Bs[TK][64 + 4];
    const int m0 = blockIdx.x * 64;
    const int n0 = blockIdx.y * 64;
    const int tid = threadIdx.x;
    const int tx = tid & 15, ty = tid >> 4;
    float acc[4][4] = {};
    for (int k0 = 0; k0 < Kdim; k0 += TK) {
#pragma unroll
        for (int e = 0; e < 4; e++) {
            int lin = tid + e * 256;
            int r = lin / TK, k = lin % TK;
            float va = 0.f, vb = 0.f;
            if (k0 + k < Kdim) {
                if (m0 + r < Mdim) va = A[(size_t)(m0 + r) * Kdim + k0 + k];
                if (n0 + r < Ndim) vb = Bw[(size_t)(n0 + r) * Kdim + k0 + k];
            }
            As[k][r] = va;
            Bs[k][r] = vb;
        }
        __syncthreads();
#pragma unroll
        for (int kk = 0; kk < TK; kk++) {
            float a[4], b[4];
#pragma unroll
            for (int i2 = 0; i2 < 4; i2++) a[i2] = As[kk][ty * 4 + i2];
#pragma unroll
            for (int j2 = 0; j2 < 4; j2++) b[j2] = Bs[kk][tx * 4 + j2];
#pragma unroll
            for (int i2 = 0; i2 < 4; i2++)
#pragma unroll
                for (int j2 = 0; j2 < 4; j2++)
                    acc[i2][j2] = fmaf(a[i2], b[j2], acc[i2][j2]);
        }
        __syncthreads();
    }
#pragma unroll
    for (int i2 = 0; i2 < 4; i2++) {
        int m = m0 + ty * 4 + i2;
        if (m >= Mdim) continue;
#pragma unroll
        for (int j2 = 0; j2 < 4; j2++) {
            int n = n0 + tx * 4 + j2;
            if (n < Ndim) C[(size_t)m * Ndim + n] = acc[i2][j2] + bias[n];
        }
    }
}

// batched gather-accumulate: acc += sum_{k in [klo,khi)} sel_d[k] * WbT_row(sel_p[k])[slot]
// 8-deep predicated load batches -> MLP=8 instead of 1.
__device__ __forceinline__ void accum_range(float4& acc, int klo, int khi, int slot,
                                            const int* __restrict__ sel_p,
                                            const float* __restrict__ sel_d)
{
    const float4* __restrict__ base = (const float4*)g_WbT;
    for (int k = klo; k < khi; k += 8) {
        const int nb = khi - k;
        float4 w[8];
#pragma unroll
        for (int b = 0; b < 8; b++)
            if (b < nb) w[b] = __ldg(base + sel_p[k + b] + slot);
#pragma unroll
        for (int b = 0; b < 8; b++)
            if (b < nb) {
                const float d = sel_d[k + b];
                acc.x = fmaf(d, w[b].x, acc.x);
                acc.y = fmaf(d, w[b].y, acc.y);
                acc.z = fmaf(d, w[b].z, acc.z);
                acc.w = fmaf(d, w[b].w, acc.w);
            }
    }
}

// ---------------- the sequential scan: single persistent CTA ----------------
__global__ void __launch_bounds__(1024, 1)
scan_kernel(const float* __restrict__ bb, float* __restrict__ tail, int B)
{
    __shared__ __align__(16) float u[TOT];     // Wb @ psi, group-A half (+ carries combined value)
    __shared__ __align__(16) float uB[TOT];    // group-B partial, folded into u in Phase A
    __shared__ float phi[TOT];
    __shared__ float psi[TOT];
    __shared__ float sig[TOT];
    __shared__ float ynew[TOT];                // sparse y scatter buffer (kept zeroed)
    __shared__ float bbs[TOT];
    __shared__ float za_s[2][MROWS];
    __shared__ __align__(16) int keys[MROWS];  // float bits of lam (all >0 -> int-order == float-order)
    __shared__ unsigned char jst[MROWS];
    __shared__ float red[32];
    __shared__ float s_smin, s_invalpha;
    __shared__ int   sel_p[64];                // row offset in float4 units (p * 300)
    __shared__ float sel_d[64];
    __shared__ int   n_sel;                    // active (d>0) deltas
    __shared__ int   n_rows;                   // rows passing the strict-> rank test

    const int tid = threadIdx.x;
    const int T = 1024;

    for (int p = tid; p < TOT; p += T) {
        u[p] = 0.f; uB[p] = 0.f; phi[p] = 0.f; psi[p] = 0.f; ynew[p] = 0.f; bbs[p] = bb[p];
    }
    if (tid < MROWS) za_s[0][tid] = g_ZA[tid];
    if (tid == 0) s_invalpha = 1.0f;
    __syncthreads();

    for (int t = 0; t < B; t++) {
        const int buf = t & 1;
        // ---- Phase A: fold uB into u; sigma = z_a + u/alpha + bb; global min ----
        float lmin = CUDART_INF_F;
        const float inva = s_invalpha;
        for (int p = tid; p < TOT; p += T) {
            float uu = u[p] + uB[p];
            u[p] = uu;
            float v = za_s[buf][p / 6] + fmaf(uu, inva, bbs[p]);
            sig[p] = v;
            lmin = fminf(lmin, v);
        }
#pragma unroll
        for (int o = 16; o; o >>= 1) lmin = fminf(lmin, __shfl_xor_sync(0xffffffffu, lmin, o));
        if ((tid & 31) == 0) red[tid >> 5] = lmin;
        __syncthreads();                                   // S1
        if (tid < 32) {
            float v = red[tid];
#pragma unroll
            for (int o = 16; o; o >>= 1) v = fminf(v, __shfl_xor_sync(0xffffffffu, v, o));
            if (tid == 0) s_smin = v;
        }
        if (tid == T - 1) { n_sel = 0; n_rows = 0; }
        __syncthreads();                                   // S2
        const float smin = s_smin;

        // ---- Phase B: per-row argmax of pi (first-index ties, like jnp.argmax) ----
        if (tid < MROWS) {
            const int i = tid;
            float best = -CUDART_INF_F; int bj = 0;
#pragma unroll
            for (int j = 0; j < 6; j++) {
                float pv = (1.0f - phi[i * 6 + j]) * (sig[i * 6 + j] - smin + 1.0f);
                if (pv > best) { best = pv; bj = j; }
            }
            jst[i] = (unsigned char)bj;
            keys[i] = __float_as_int(best);                // lam > 0 always
        } else if (tid >= 256 && tid < 256 + MROWS) {
            int i2 = tid - 256;                            // prefetch next z_a row
            if (t + 1 < B) za_s[buf ^ 1][i2] = g_ZA[(size_t)(t + 1) * MROWS + i2];
        }
        __syncthreads();                                   // S3

        // ---- Phase C: top-25 selection via strict-greater rank counting ----
        if (tid < MROWS) {
            const int i = tid;
            const int ki = keys[i];
            int cnt = 0;
            const int4* k4 = (const int4*)keys;
#pragma unroll 10
            for (int j4 = 0; j4 < MROWS / 4; j4++) {
                int4 kk = k4[j4];
                cnt += (kk.x > ki) + (kk.y > ki) + (kk.z > ki) + (kk.w > ki);
            }
            float ym = 0.0f;
            if (cnt < KSEL) {
                atomicAdd(&n_rows, 1);
                int p = i * 6 + (int)jst[i];
                float yv = tanhf(sig[p]);
                ym = fmaxf(yv, 0.0f);
                ynew[p] = yv;
                float d = yv - 0.5f * psi[p];
                if (d > 0.0f) {                            // zero deltas contribute nothing
                    int slot = atomicAdd(&n_sel, 1);
                    if (slot < 64) { sel_p[slot] = p * (TOT / 4); sel_d[slot] = d; }
                }
            }
            g_Ymax[(size_t)t * MROWS + i] = ym;
        }
        __syncthreads();                                   // S4

        // ---- Rare exact-tie fallback (selected row count != 25) ----
        if (n_rows != KSEL) {
            for (int p = tid; p < TOT; p += T) ynew[p] = 0.0f;
            __syncthreads();
            if (tid == 0) { n_sel = 0; n_rows = 0; }
            __syncthreads();
            if (tid < MROWS) {
                const int i = tid;
                const int ki = keys[i];
                int cnt = 0;
                for (int j = 0; j < MROWS; j++) {
                    int kj = keys[j];
                    cnt += (kj > ki) || (kj == ki && j < i);  // lax.top_k tie rule
                }
                float ym = 0.0f;
                if (cnt < KSEL) {
                    int p = i * 6 + (int)jst[i];
                    float yv = tanhf(sig[p]);
                    ym = fmaxf(yv, 0.0f);
                    ynew[p] = yv;
                    float d = yv - 0.5f * psi[p];
                    if (d > 0.0f) {
                        int slot = atomicAdd(&n_sel, 1);
                        sel_p[slot] = p * (TOT / 4); sel_d[slot] = d;
                    }
                }
                g_Ymax[(size_t)t * MROWS + i] = ym;
            }
            __syncthreads();
        }

        // ---- Phase D (3-way overlap):
        //   warps  0- 9: u  = 0.5*u + sum over k in [0,half)
        //   warps 10-19: uB =         sum over k in [half,ns)
        //   warps 20-31: psi/phi decay+apply, alpha partial sums
        const int ns = n_sel;
        const int half = (ns + 1) >> 1;
        if (tid < 320) {
            if (tid < TOT / 4) {
                float4* u4 = (float4*)u;
                float4 acc = u4[tid];
                acc.x *= 0.5f; acc.y *= 0.5f; acc.z *= 0.5f; acc.w *= 0.5f;
                accum_range(acc, 0, half, tid, sel_p, sel_d);
                u4[tid] = acc;
            }
        } else if (tid < 640) {
            const int s = tid - 320;
            if (s < TOT / 4) {
                float4* uB4 = (float4*)uB;
                float4 acc = make_float4(0.f, 0.f, 0.f, 0.f);
                accum_range(acc, half, ns, s, sel_p, sel_d);
                uB4[s] = acc;
            }
        } else {
            float part = 0.0f;
            for (int p = tid - 640; p < TOT; p += 384) {
                float nv = ynew[p];
                float ps = fmaxf(0.5f * psi[p], nv);
                psi[p] = ps;
                phi[p] = fmaxf(0.5f * phi[p], nv);
                ynew[p] = 0.0f;
                part += ps;
            }
#pragma unroll
            for (int o = 16; o; o >>= 1) part += __shfl_xor_sync(0xffffffffu, part, o);
            if ((tid & 31) == 0) red[(tid >> 5) - 20] = part;
        }
        __syncthreads();                                   // S5
        if (tid < 32) {
            float v = (tid < 12) ? red[tid] : 0.0f;
#pragma unroll
            for (int o = 16; o; o >>= 1) v += __shfl_xor_sync(0xffffffffu, v, o);
            if (tid == 0) {
                float a = (v == 0.0f) ? 1.0f : v;
                s_invalpha = 1.0f / a;
            }
        }
        __syncthreads();                                   // S6
    }

    // final carry outputs: x_b = psi/alpha, phi, psi
    const float inva = s_invalpha;
    for (int p = tid; p < TOT; p += T) {
        tail[p]            = psi[p] * inva;
        tail[TOT + p]      = phi[p];
        tail[2 * TOT + p]  = psi[p];
    }
}

// ---------------- launch ----------------
extern "C" void kernel_launch(void* const* d_in, const int* in_sizes, int n_in,
                              void* d_out, int out_size)
{
    const float* batch_x = (const float*)d_in[0];   // (B, 784)
    const float* Wa      = (const float*)d_in[1];   // (200, 784)
    const float* ba      = (const float*)d_in[2];   // (200,)
    const float* Wb      = (const float*)d_in[3];   // (1200, 1200)
    const float* bb      = (const float*)d_in[4];   // (1200,)
    const float* Wd      = (const float*)d_in[5];   // (784, 200)
    const float* bd      = (const float*)d_in[6];   // (784,)
    float* out = (float*)d_out;

    const int B = in_sizes[0] / DIN;

    float *pZA = nullptr, *pYmax = nullptr;
    cudaGetSymbolAddress((void**)&pZA, g_ZA);
    cudaGetSymbolAddress((void**)&pYmax, g_Ymax);

    // 1) Wb transpose for coalesced column gathers
    {
        dim3 tb(32, 8);
        dim3 tg((TOT + 31) / 32, (TOT + 31) / 32);
        transpose_wb<<<tg, tb>>>(Wb);
    }
    // 2) hoisted input GEMM: ZA[t][i] = Wa[i,:] . x_t + ba[i]
    {
        dim3 grid((B + 63) / 64, (MROWS + 63) / 64);
        gemm_abt_kernel<<<grid, 256>>>(batch_x, Wa, ba, pZA, B, MROWS, DIN);
    }
    // 3) sequential scan (records Ymax, writes carry tail)
    scan_kernel<<<1, 1024>>>(bb, out + (size_t)B * DIN, B);
    // 4) deferred output GEMM: preds[t][d] = Wd[d,:] . ymax_t + bd[d]
    {
        dim3 grid((B + 63) / 64, (DIN + 63) / 64);
        gemm_abt_kernel<<<grid, 256>>>(pYmax, Wd, bd, out, B, DIN, MROWS);
    }
}

// round 3
// speedup vs baseline: 1.7794x; 1.7794x over previous
#include <cuda_runtime.h>
#include <math_constants.h>
#include <cstdint>

#define MROWS 200
#define NCOLS 6
#define TOT   1200   // MROWS*NCOLS
#define KSEL  25
#define DIN   784
#define BMAX  16384

// ---------------- device scratch (static; no runtime allocation) ----------------
__device__ float g_WbT[TOT * TOT];          // Wb transposed: column c of Wb = row c of WbT
__device__ float g_ZA[BMAX * MROWS];        // precomputed Wa@x_t + ba
__device__ float g_Ymax[BMAX * MROWS];      // recorded y.max(axis=1) per step

// ---------------- transpose Wb -> g_WbT ----------------
__global__ void transpose_wb(const float* __restrict__ Wb) {
    __shared__ float tile[32][33];
    int bx = blockIdx.x * 32, by = blockIdx.y * 32;
    int x = bx + threadIdx.x;
    if (x < TOT) {
        for (int dy = 0; dy < 32; dy += 8) {
            int yy = by + threadIdx.y + dy;
            if (yy < TOT) tile[threadIdx.y + dy][threadIdx.x] = Wb[(size_t)yy * TOT + x];
        }
    }
    __syncthreads();
    int r = by + threadIdx.x;
    if (r < TOT) {
        for (int dy = 0; dy < 32; dy += 8) {
            int c = bx + threadIdx.y + dy;
            if (c < TOT) g_WbT[(size_t)c * TOT + r] = tile[threadIdx.x][threadIdx.y + dy];
        }
    }
}

// ---------------- generic C[M,N] = A[M,K] @ B[N,K]^T + bias[N] ----------------
__global__ void gemm_abt_kernel(const float* __restrict__ A, const float* __restrict__ Bw,
                                const float* __restrict__ bias, float* __restrict__ C,
                                int Mdim, int Ndim, int Kdim)
{
    const int TK = 16;
    __shared__ float As[TK][64 + 4];
    __shared__ float Bs[TK][64 + 4];
    const int m0 = blockIdx.x * 64;
    const int n0 = blockIdx.y * 64;
    const int tid = threadIdx.x;
    const int tx = tid & 15, ty = tid >> 4;
    float acc[4][4] = {};
    for (int k0 = 0; k0 < Kdim; k0 += TK) {
#pragma unroll
        for (int e = 0; e < 4; e++) {
            int lin = tid + e * 256;
            int r = lin / TK, k = lin % TK;
            float va = 0.f, vb = 0.f;
            if (k0 + k < Kdim) {
                if (m0 + r < Mdim) va = A[(size_t)(m0 + r) * Kdim + k0 + k];
                if (n0 + r < Ndim) vb = Bw[(size_t)(n0 + r) * Kdim + k0 + k];
            }
            As[k][r] = va;
            Bs[k][r] = vb;
        }
        __syncthreads();
#pragma unroll
        for (int kk = 0; kk < TK; kk++) {
            float a[4], b[4];
#pragma unroll
            for (int i2 = 0; i2 < 4; i2++) a[i2] = As[kk][ty * 4 + i2];
#pragma unroll
            for (int j2 = 0; j2 < 4; j2++) b[j2] = Bs[kk][tx * 4 + j2];
#pragma unroll
            for (int i2 = 0; i2 < 4; i2++)
#pragma unroll
                for (int j2 = 0; j2 < 4; j2++)
                    acc[i2][j2] = fmaf(a[i2], b[j2], acc[i2][j2]);
        }
        __syncthreads();
    }
#pragma unroll
    for (int i2 = 0; i2 < 4; i2++) {
        int m = m0 + ty * 4 + i2;
        if (m >= Mdim) continue;
#pragma unroll
        for (int j2 = 0; j2 < 4; j2++) {
            int n = n0 + tx * 4 + j2;
            if (n < Ndim) C[(size_t)m * Ndim + n] = acc[i2][j2] + bias[n];
        }
    }
}

// gather 9 rows for one slot: waves of 5 then 4 unconditional loads (<=20 regs live)
__device__ __forceinline__ void accum9(float4& acc, int kbase, int slot,
                                       const int* __restrict__ sel_p,
                                       const float* __restrict__ sel_d)
{
    const float4* __restrict__ base = (const float4*)g_WbT;
    {
        float4 w0 = __ldg(base + sel_p[kbase + 0] + slot);
        float4 w1 = __ldg(base + sel_p[kbase + 1] + slot);
        float4 w2 = __ldg(base + sel_p[kbase + 2] + slot);
        float4 w3 = __ldg(base + sel_p[kbase + 3] + slot);
        float4 w4 = __ldg(base + sel_p[kbase + 4] + slot);
        float d0 = sel_d[kbase + 0], d1 = sel_d[kbase + 1], d2 = sel_d[kbase + 2];
        float d3 = sel_d[kbase + 3], d4 = sel_d[kbase + 4];
        acc.x = fmaf(d0, w0.x, acc.x); acc.y = fmaf(d0, w0.y, acc.y);
        acc.z = fmaf(d0, w0.z, acc.z); acc.w = fmaf(d0, w0.w, acc.w);
        acc.x = fmaf(d1, w1.x, acc.x); acc.y = fmaf(d1, w1.y, acc.y);
        acc.z = fmaf(d1, w1.z, acc.z); acc.w = fmaf(d1, w1.w, acc.w);
        acc.x = fmaf(d2, w2.x, acc.x); acc.y = fmaf(d2, w2.y, acc.y);
        acc.z = fmaf(d2, w2.z, acc.z); acc.w = fmaf(d2, w2.w, acc.w);
        acc.x = fmaf(d3, w3.x, acc.x); acc.y = fmaf(d3, w3.y, acc.y);
        acc.z = fmaf(d3, w3.z, acc.z); acc.w = fmaf(d3, w3.w, acc.w);
        acc.x = fmaf(d4, w4.x, acc.x); acc.y = fmaf(d4, w4.y, acc.y);
        acc.z = fmaf(d4, w4.z, acc.z); acc.w = fmaf(d4, w4.w, acc.w);
    }
    {
        float4 w0 = __ldg(base + sel_p[kbase + 5] + slot);
        float4 w1 = __ldg(base + sel_p[kbase + 6] + slot);
        float4 w2 = __ldg(base + sel_p[kbase + 7] + slot);
        float4 w3 = __ldg(base + sel_p[kbase + 8] + slot);
        float d0 = sel_d[kbase + 5], d1 = sel_d[kbase + 6];
        float d2 = sel_d[kbase + 7], d3 = sel_d[kbase + 8];
        acc.x = fmaf(d0, w0.x, acc.x); acc.y = fmaf(d0, w0.y, acc.y);
        acc.z = fmaf(d0, w0.z, acc.z); acc.w = fmaf(d0, w0.w, acc.w);
        acc.x = fmaf(d1, w1.x, acc.x); acc.y = fmaf(d1, w1.y, acc.y);
        acc.z = fmaf(d1, w1.z, acc.z); acc.w = fmaf(d1, w1.w, acc.w);
        acc.x = fmaf(d2, w2.x, acc.x); acc.y = fmaf(d2, w2.y, acc.y);
        acc.z = fmaf(d2, w2.z, acc.z); acc.w = fmaf(d2, w2.w, acc.w);
        acc.x = fmaf(d3, w3.x, acc.x); acc.y = fmaf(d3, w3.y, acc.y);
        acc.z = fmaf(d3, w3.z, acc.z); acc.w = fmaf(d3, w3.w, acc.w);
    }
}

// ---------------- the sequential scan: single persistent CTA ----------------
__global__ void __launch_bounds__(1024, 1)
scan_kernel(const float* __restrict__ bb, float* __restrict__ tail, int B)
{
    __shared__ __align__(16) float u[TOT];     // combined Wb@psi after Phase-A fold
    __shared__ __align__(16) float uB[TOT];    // group-1 partial
    __shared__ __align__(16) float uC[TOT];    // group-2 partial
    __shared__ float phi[TOT];
    __shared__ float psi[TOT];
    __shared__ float sig[TOT];
    __shared__ float ynew[TOT];
    __shared__ float bbs[TOT];
    __shared__ float za_s[2][MROWS];
    __shared__ __align__(16) int keys[MROWS];  // float bits of lam (>0 -> int order == float order)
    __shared__ unsigned char jst[MROWS];
    __shared__ float red[32];
    __shared__ float s_smin, s_invalpha;
    __shared__ int   sel_p[32];                // row offset in float4 units (p * 300); padded with 0
    __shared__ float sel_d[32];                // padded with 0.0f
    __shared__ int   n_sel;

    const int tid = threadIdx.x;
    const int T = 1024;

    for (int p = tid; p < TOT; p += T) {
        u[p] = 0.f; uB[p] = 0.f; uC[p] = 0.f;
        phi[p] = 0.f; psi[p] = 0.f; ynew[p] = 0.f; bbs[p] = bb[p];
    }
    if (tid < 32) { sel_p[tid] = 0; sel_d[tid] = 0.f; }
    if (tid < MROWS) za_s[0][tid] = g_ZA[tid];
    if (tid == 0) s_invalpha = 1.0f;
    __syncthreads();

    for (int t = 0; t < B; t++) {
        const int buf = t & 1;
        // ---- Phase A: fold partials; sigma = z_a + u*inva + bb; global min ----
        float lmin = CUDART_INF_F;
        const float inva = s_invalpha;
        for (int p = tid; p < TOT; p += T) {
            float uu = u[p] + uB[p] + uC[p];
            u[p] = uu;
            float v = za_s[buf][p / 6] + fmaf(uu, inva, bbs[p]);
            sig[p] = v;
            lmin = fminf(lmin, v);
        }
#pragma unroll
        for (int o = 16; o; o >>= 1) lmin = fminf(lmin, __shfl_xor_sync(0xffffffffu, lmin, o));
        if ((tid & 31) == 0) red[tid >> 5] = lmin;
        if (tid == T - 1) n_sel = 0;
        __syncthreads();                                   // S1
        if (tid < 32) {
            float v = red[tid];
#pragma unroll
            for (int o = 16; o; o >>= 1) v = fminf(v, __shfl_xor_sync(0xffffffffu, v, o));
            if (tid == 0) s_smin = v;
        }
        __syncthreads();                                   // S2
        const float smin = s_smin;

        // ---- Phase B: per-row argmax of pi (first-index ties, like jnp.argmax);
        //      idle ranges clear selection-list padding and prefetch next z_a ----
        if (tid < MROWS) {
            const int i = tid;
            float best = -CUDART_INF_F; int bj = 0;
#pragma unroll
            for (int j = 0; j < 6; j++) {
                float pv = (1.0f - phi[i * 6 + j]) * (sig[i * 6 + j] - smin + 1.0f);
                if (pv > best) { best = pv; bj = j; }
            }
            jst[i] = (unsigned char)bj;
            keys[i] = __float_as_int(best);
        } else if (tid < 232) {
            sel_p[tid - 200] = 0; sel_d[tid - 200] = 0.f;  // zero padding slots each step
        } else if (tid >= 256 && tid < 256 + MROWS) {
            int i2 = tid - 256;
            if (t + 1 < B) za_s[buf ^ 1][i2] = g_ZA[(size_t)(t + 1) * MROWS + i2];
        }
        __syncthreads();                                   // S3

        // ---- Phase C: top-25 via strict-greater rank counting ----
        int pred = 0;
        if (tid < MROWS) {
            const int i = tid;
            const int ki = keys[i];
            int cnt = 0;
            const int4* k4 = (const int4*)keys;
#pragma unroll 10
            for (int j4 = 0; j4 < MROWS / 4; j4++) {
                int4 kk = k4[j4];
                cnt += (kk.x > ki) + (kk.y > ki) + (kk.z > ki) + (kk.w > ki);
            }
            float ym = 0.0f;
            if (cnt < KSEL) {
                pred = 1;
                int p = i * 6 + (int)jst[i];
                float yv = tanhf(sig[p]);
                ym = fmaxf(yv, 0.0f);
                ynew[p] = yv;
                float d = yv - 0.5f * psi[p];
                if (d > 0.0f) {
                    int slot = atomicAdd(&n_sel, 1);
                    if (slot < 32) { sel_p[slot] = p * (TOT / 4); sel_d[slot] = d; }
                }
            }
            g_Ymax[(size_t)t * MROWS + i] = ym;
        }
        const int nr = __syncthreads_count(pred);          // S4 (barrier + count)

        // ---- Rare exact-tie fallback (selected row count != 25) ----
        if (nr != KSEL) {
            for (int p = tid; p < TOT; p += T) ynew[p] = 0.0f;
            if (tid < 32) { sel_p[tid] = 0; sel_d[tid] = 0.f; }
            if (tid == 0) n_sel = 0;
            __syncthreads();
            if (tid < MROWS) {
                const int i = tid;
                const int ki = keys[i];
                int cnt = 0;
                for (int j = 0; j < MROWS; j++) {
                    int kj = keys[j];
                    cnt += (kj > ki) || (kj == ki && j < i);  // lax.top_k tie rule
                }
                float ym = 0.0f;
                if (cnt < KSEL) {
                    int p = i * 6 + (int)jst[i];
                    float yv = tanhf(sig[p]);
                    ym = fmaxf(yv, 0.0f);
                    ynew[p] = yv;
                    float d = yv - 0.5f * psi[p];
                    if (d > 0.0f) {
                        int slot = atomicAdd(&n_sel, 1);
                        sel_p[slot] = p * (TOT / 4); sel_d[slot] = d;
                    }
                }
                g_Ymax[(size_t)t * MROWS + i] = ym;
            }
            __syncthreads();
        }

        // ---- Phase D (4-way overlap): warps 0-9 / 10-19 / 20-29 gather k-ranges
        //      [0,9) [9,18) [18,27) (padded); warps 30-31 do psi/phi + alpha ----
        if (tid < 960) {
            const int g = tid >> 5 >= 20 ? 2 : (tid >> 5 >= 10 ? 1 : 0);
            const int slot = tid - g * 320;
            if (slot < TOT / 4) {
                if (g == 0) {
                    float4* u4 = (float4*)u;
                    float4 acc = u4[slot];
                    acc.x *= 0.5f; acc.y *= 0.5f; acc.z *= 0.5f; acc.w *= 0.5f;
                    accum9(acc, 0, slot, sel_p, sel_d);
                    u4[slot] = acc;
                } else if (g == 1) {
                    float4 acc = make_float4(0.f, 0.f, 0.f, 0.f);
                    accum9(acc, 9, slot, sel_p, sel_d);
                    ((float4*)uB)[slot] = acc;
                } else {
                    float4 acc = make_float4(0.f, 0.f, 0.f, 0.f);
                    accum9(acc, 18, slot, sel_p, sel_d);
                    ((float4*)uC)[slot] = acc;
                }
            }
        } else {
            float part = 0.0f;
            for (int p = tid - 960; p < TOT; p += 64) {
                float nv = ynew[p];
                float ps = fmaxf(0.5f * psi[p], nv);
                psi[p] = ps;
                phi[p] = fmaxf(0.5f * phi[p], nv);
                ynew[p] = 0.0f;
                part += ps;
            }
#pragma unroll
            for (int o = 16; o; o >>= 1) part += __shfl_xor_sync(0xffffffffu, part, o);
            if ((tid & 31) == 0) red[(tid >> 5) - 30] = part;
        }
        __syncthreads();                                   // S5
        if (tid < 32) {
            float v = (tid < 2) ? red[tid] : 0.0f;
#pragma unroll
            for (int o = 16; o; o >>= 1) v += __shfl_xor_sync(0xffffffffu, v, o);
            if (tid == 0) {
                float a = (v == 0.0f) ? 1.0f : v;
                s_invalpha = 1.0f / a;
            }
        }
        __syncthreads();                                   // S6
    }

    // final carry outputs: x_b = psi/alpha, phi, psi
    const float inva = s_invalpha;
    for (int p = tid; p < TOT; p += T) {
        tail[p]            = psi[p] * inva;
        tail[TOT + p]      = phi[p];
        tail[2 * TOT + p]  = psi[p];
    }
}

// ---------------- launch ----------------
extern "C" void kernel_launch(void* const* d_in, const int* in_sizes, int n_in,
                              void* d_out, int out_size)
{
    const float* batch_x = (const float*)d_in[0];   // (B, 784)
    const float* Wa      = (const float*)d_in[1];   // (200, 784)
    const float* ba      = (const float*)d_in[2];   // (200,)
    const float* Wb      = (const float*)d_in[3];   // (1200, 1200)
    const float* bb      = (const float*)d_in[4];   // (1200,)
    const float* Wd      = (const float*)d_in[5];   // (784, 200)
    const float* bd      = (const float*)d_in[6];   // (784,)
    float* out = (float*)d_out;

    const int B = in_sizes[0] / DIN;

    float *pZA = nullptr, *pYmax = nullptr;
    cudaGetSymbolAddress((void**)&pZA, g_ZA);
    cudaGetSymbolAddress((void**)&pYmax, g_Ymax);

    // 1) Wb transpose for coalesced column gathers
    {
        dim3 tb(32, 8);
        dim3 tg((TOT + 31) / 32, (TOT + 31) / 32);
        transpose_wb<<<tg, tb>>>(Wb);
    }
    // 2) hoisted input GEMM: ZA[t][i] = Wa[i,:] . x_t + ba[i]
    {
        dim3 grid((B + 63) / 64, (MROWS + 63) / 64);
        gemm_abt_kernel<<<grid, 256>>>(batch_x, Wa, ba, pZA, B, MROWS, DIN);
    }
    // 3) sequential scan (records Ymax, writes carry tail)
    scan_kernel<<<1, 1024>>>(bb, out + (size_t)B * DIN, B);
    // 4) deferred output GEMM: preds[t][d] = Wd[d,:] . ymax_t + bd[d]
    {
        dim3 grid((B + 63) / 64, (DIN + 63) / 64);
        gemm_abt_kernel<<<grid, 256>>>(pYmax, Wd, bd, out, B, DIN, MROWS);
    }
}

// round 5
// speedup vs baseline: 1.9552x; 1.0988x over previous
#include <cuda_runtime.h>
#include <math_constants.h>
#include <cstdint>

#define MROWS 200
#define NCOLS 6
#define TOT   1200   // MROWS*NCOLS
#define KSEL  25
#define DIN   784
#define BMAX  16384

// ---------------- device scratch (static; no runtime allocation) ----------------
__device__ float g_WbT[TOT * TOT];          // Wb transposed: column c of Wb = row c of WbT
__device__ float g_ZA[BMAX * MROWS];        // precomputed Wa@x_t + ba
__device__ float g_Ymax[BMAX * MROWS];      // recorded y.max(axis=1) per step

// ---------------- transpose Wb -> g_WbT ----------------
__global__ void transpose_wb(const float* __restrict__ Wb) {
    __shared__ float tile[32][33];
    int bx = blockIdx.x * 32, by = blockIdx.y * 32;
    int x = bx + threadIdx.x;
    if (x < TOT) {
        for (int dy = 0; dy < 32; dy += 8) {
            int yy = by + threadIdx.y + dy;
            if (yy < TOT) tile[threadIdx.y + dy][threadIdx.x] = Wb[(size_t)yy * TOT + x];
        }
    }
    __syncthreads();
    int r = by + threadIdx.x;
    if (r < TOT) {
        for (int dy = 0; dy < 32; dy += 8) {
            int c = bx + threadIdx.y + dy;
            if (c < TOT) g_WbT[(size_t)c * TOT + r] = tile[threadIdx.x][threadIdx.y + dy];
        }
    }
}

// ---------------- generic C[M,N] = A[M,K] @ B[N,K]^T + bias[N] ----------------
__global__ void gemm_abt_kernel(const float* __restrict__ A, const float* __restrict__ Bw,
                                const float* __restrict__ bias, float* __restrict__ C,
                                int Mdim, int Ndim, int Kdim)
{
    const int TK = 16;
    __shared__ float As[TK][64 + 4];
    __shared__ float Bs[TK][64 + 4];
    const int m0 = blockIdx.x * 64;
    const int n0 = blockIdx.y * 64;
    const int tid = threadIdx.x;
    const int tx = tid & 15, ty = tid >> 4;
    float acc[4][4] = {};
    for (int k0 = 0; k0 < Kdim; k0 += TK) {
#pragma unroll
        for (int e = 0; e < 4; e++) {
            int lin = tid + e * 256;
            int r = lin / TK, k = lin % TK;
            float va = 0.f, vb = 0.f;
            if (k0 + k < Kdim) {
                if (m0 + r < Mdim) va = A[(size_t)(m0 + r) * Kdim + k0 + k];
                if (n0 + r < Ndim) vb = Bw[(size_t)(n0 + r) * Kdim + k0 + k];
            }
            As[k][r] = va;
            Bs[k][r] = vb;
        }
        __syncthreads();
#pragma unroll
        for (int kk = 0; kk < TK; kk++) {
            float a[4], b[4];
#pragma unroll
            for (int i2 = 0; i2 < 4; i2++) a[i2] = As[kk][ty * 4 + i2];
#pragma unroll
            for (int j2 = 0; j2 < 4; j2++) b[j2] = Bs[kk][tx * 4 + j2];
#pragma unroll
            for (int i2 = 0; i2 < 4; i2++)
#pragma unroll
                for (int j2 = 0; j2 < 4; j2++)
                    acc[i2][j2] = fmaf(a[i2], b[j2], acc[i2][j2]);
        }
        __syncthreads();
    }
#pragma unroll
    for (int i2 = 0; i2 < 4; i2++) {
        int m = m0 + ty * 4 + i2;
        if (m >= Mdim) continue;
#pragma unroll
        for (int j2 = 0; j2 < 4; j2++) {
            int n = n0 + tx * 4 + j2;
            if (n < Ndim) C[(size_t)m * Ndim + n] = acc[i2][j2] + bias[n];
        }
    }
}

#define NAMED_BAR(id, cnt) asm volatile("bar.sync %0, %1;" :: "r"(id), "r"(cnt) : "memory")

// gather 9 rows for one slot: waves of 5 then 4 unconditional loads (<=20 regs live)
__device__ __forceinline__ void accum9(float4& acc, int kbase, int slot,
                                       const int* __restrict__ sel_p,
                                       const float* __restrict__ sel_d)
{
    const float4* __restrict__ base = (const float4*)g_WbT;
    {
        float4 w0 = __ldg(base + sel_p[kbase + 0] + slot);
        float4 w1 = __ldg(base + sel_p[kbase + 1] + slot);
        float4 w2 = __ldg(base + sel_p[kbase + 2] + slot);
        float4 w3 = __ldg(base + sel_p[kbase + 3] + slot);
        float4 w4 = __ldg(base + sel_p[kbase + 4] + slot);
        float d0 = sel_d[kbase + 0], d1 = sel_d[kbase + 1], d2 = sel_d[kbase + 2];
        float d3 = sel_d[kbase + 3], d4 = sel_d[kbase + 4];
        acc.x = fmaf(d0, w0.x, acc.x); acc.y = fmaf(d0, w0.y, acc.y);
        acc.z = fmaf(d0, w0.z, acc.z); acc.w = fmaf(d0, w0.w, acc.w);
        acc.x = fmaf(d1, w1.x, acc.x); acc.y = fmaf(d1, w1.y, acc.y);
        acc.z = fmaf(d1, w1.z, acc.z); acc.w = fmaf(d1, w1.w, acc.w);
        acc.x = fmaf(d2, w2.x, acc.x); acc.y = fmaf(d2, w2.y, acc.y);
        acc.z = fmaf(d2, w2.z, acc.z); acc.w = fmaf(d2, w2.w, acc.w);
        acc.x = fmaf(d3, w3.x, acc.x); acc.y = fmaf(d3, w3.y, acc.y);
        acc.z = fmaf(d3, w3.z, acc.z); acc.w = fmaf(d3, w3.w, acc.w);
        acc.x = fmaf(d4, w4.x, acc.x); acc.y = fmaf(d4, w4.y, acc.y);
        acc.z = fmaf(d4, w4.z, acc.z); acc.w = fmaf(d4, w4.w, acc.w);
    }
    {
        float4 w0 = __ldg(base + sel_p[kbase + 5] + slot);
        float4 w1 = __ldg(base + sel_p[kbase + 6] + slot);
        float4 w2 = __ldg(base + sel_p[kbase + 7] + slot);
        float4 w3 = __ldg(base + sel_p[kbase + 8] + slot);
        float d0 = sel_d[kbase + 5], d1 = sel_d[kbase + 6];
        float d2 = sel_d[kbase + 7], d3 = sel_d[kbase + 8];
        acc.x = fmaf(d0, w0.x, acc.x); acc.y = fmaf(d0, w0.y, acc.y);
        acc.z = fmaf(d0, w0.z, acc.z); acc.w = fmaf(d0, w0.w, acc.w);
        acc.x = fmaf(d1, w1.x, acc.x); acc.y = fmaf(d1, w1.y, acc.y);
        acc.z = fmaf(d1, w1.z, acc.z); acc.w = fmaf(d1, w1.w, acc.w);
        acc.x = fmaf(d2, w2.x, acc.x); acc.y = fmaf(d2, w2.y, acc.y);
        acc.z = fmaf(d2, w2.z, acc.z); acc.w = fmaf(d2, w2.w, acc.w);
        acc.x = fmaf(d3, w3.x, acc.x); acc.y = fmaf(d3, w3.y, acc.y);
        acc.z = fmaf(d3, w3.z, acc.z); acc.w = fmaf(d3, w3.w, acc.w);
    }
}

// ---------------- the sequential scan: single persistent CTA, 3 full barriers/step ----------------
__global__ void __launch_bounds__(1024, 1)
scan_kernel(const float* __restrict__ bb, float* __restrict__ tail, int B)
{
    __shared__ __align__(16) float u[TOT];     // combined Wb@psi after Phase-A fold
    __shared__ __align__(16) float uB[TOT];    // group-1 partial
    __shared__ __align__(16) float uC[TOT];    // group-2 partial
    __shared__ float phi[TOT];
    __shared__ float psi[TOT];
    __shared__ float sig[TOT];
    __shared__ float ynew[TOT];
    __shared__ float bbs[TOT];
    __shared__ float za_s[2][MROWS];
    __shared__ __align__(16) int keys[MROWS];  // float bits of lam (>0 -> int order == float order)
    __shared__ unsigned char jst[MROWS];
    __shared__ float red_min[32];
    __shared__ float red_alpha[2];
    __shared__ float s_invalpha;
    __shared__ int   sel_p[32];                // row offset in float4 units (p * 300); padded with 0
    __shared__ float sel_d[32];                // padded with 0.0f
    __shared__ int   n_sel;

    const int tid = threadIdx.x;
    const int T = 1024;
    const int lane = tid & 31;

    for (int p = tid; p < TOT; p += T) {
        u[p] = 0.f; uB[p] = 0.f; uC[p] = 0.f;
        phi[p] = 0.f; psi[p] = 0.f; ynew[p] = 0.f; bbs[p] = bb[p];
    }
    if (tid < 32) { sel_p[tid] = 0; sel_d[tid] = 0.f; }
    if (tid < MROWS) za_s[0][tid] = g_ZA[tid];
    if (tid == 0) s_invalpha = 1.0f;
    __syncthreads();

    for (int t = 0; t < B; t++) {
        const int buf = t & 1;
        // ---- Phase A: fold partials; sigma = z_a + u*inva + bb; warp-partial min ----
        const float inva = s_invalpha;
        float lmin;
        {
            int p = tid;
            float uu = u[p] + uB[p] + uC[p];
            u[p] = uu;
            float v = za_s[buf][p / 6] + fmaf(uu, inva, bbs[p]);
            sig[p] = v;
            lmin = v;
        }
        if (tid < TOT - T) {
            int p = tid + T;
            float uu = u[p] + uB[p] + uC[p];
            u[p] = uu;
            float v = za_s[buf][p / 6] + fmaf(uu, inva, bbs[p]);
            sig[p] = v;
            lmin = fminf(lmin, v);
        }
#pragma unroll
        for (int o = 16; o; o >>= 1) lmin = fminf(lmin, __shfl_xor_sync(0xffffffffu, lmin, o));
        if (lane == 0) red_min[tid >> 5] = lmin;
        __syncthreads();                                   // S1 (full)

        // redundant stage-2: every warp locally reduces red_min[32] -> smin
        float smin = red_min[lane];
#pragma unroll
        for (int o = 16; o; o >>= 1) smin = fminf(smin, __shfl_xor_sync(0xffffffffu, smin, o));

        // ---- Phase B (threads 0-255, named barrier): argmax per row; housekeeping ----
        if (tid < 256) {
            if (tid < MROWS) {
                const int i = tid;
                float best = -CUDART_INF_F; int bj = 0;
#pragma unroll
                for (int j = 0; j < 6; j++) {
                    float pv = (1.0f - phi[i * 6 + j]) * (sig[i * 6 + j] - smin + 1.0f);
                    if (pv > best) { best = pv; bj = j; }
                }
                jst[i] = (unsigned char)bj;
                keys[i] = __float_as_int(best);
            } else if (tid < 232) {
                sel_p[tid - 200] = 0; sel_d[tid - 200] = 0.f;  // zero padding slots each step
            } else if (tid == 232) {
                n_sel = 0;
            }
            NAMED_BAR(1, 256);                             // NB1: keys/jst/sel-reset visible to C

            // ---- Phase C (threads 0-199): top-25 via strict-greater rank counting ----
        } else if (tid >= 256 && tid < 256 + MROWS) {
            int i2 = tid - 256;                            // prefetch next z_a row
            if (t + 1 < B) za_s[buf ^ 1][i2] = g_ZA[(size_t)(t + 1) * MROWS + i2];
        }

        int pred = 0;
        if (tid < MROWS) {
            const int i = tid;
            const int ki = keys[i];
            int cnt = 0;
            const int4* k4 = (const int4*)keys;
#pragma unroll 10
            for (int j4 = 0; j4 < MROWS / 4; j4++) {
                int4 kk = k4[j4];
                cnt += (kk.x > ki) + (kk.y > ki) + (kk.z > ki) + (kk.w > ki);
            }
            float ym = 0.0f;
            if (cnt < KSEL) {
                pred = 1;
                int p = i * 6 + (int)jst[i];
                float yv = tanhf(sig[p]);
                ym = fmaxf(yv, 0.0f);
                ynew[p] = yv;
                float d = yv - 0.5f * psi[p];
                if (d > 0.0f) {
                    int slot = atomicAdd(&n_sel, 1);
                    if (slot < 32) { sel_p[slot] = p * (TOT / 4); sel_d[slot] = d; }
                }
            }
            g_Ymax[(size_t)t * MROWS + i] = ym;
        }
        const int nr = __syncthreads_count(pred);          // S4 (full barrier + count)

        // ---- Rare exact-tie fallback (selected row count != 25) ----
        if (nr != KSEL) {
            for (int p = tid; p < TOT; p += T) ynew[p] = 0.0f;
            if (tid < 32) { sel_p[tid] = 0; sel_d[tid] = 0.f; }
            if (tid == 0) n_sel = 0;
            __syncthreads();
            if (tid < MROWS) {
                const int i = tid;
                const int ki = keys[i];
                int cnt = 0;
                for (int j = 0; j < MROWS; j++) {
                    int kj = keys[j];
                    cnt += (kj > ki) || (kj == ki && j < i);  // lax.top_k tie rule
                }
                float ym = 0.0f;
                if (cnt < KSEL) {
                    int p = i * 6 + (int)jst[i];
                    float yv = tanhf(sig[p]);
                    ym = fmaxf(yv, 0.0f);
                    ynew[p] = yv;
                    float d = yv - 0.5f * psi[p];
                    if (d > 0.0f) {
                        int slot = atomicAdd(&n_sel, 1);
                        sel_p[slot] = p * (TOT / 4); sel_d[slot] = d;
                    }
                }
                g_Ymax[(size_t)t * MROWS + i] = ym;
            }
            __syncthreads();
        }

        // ---- Phase D (4-way overlap): warps 0-9 / 10-19 / 20-29 gather k-ranges
        //      [0,9) [9,18) [18,27) (padded); warps 30-31 do psi/phi + alpha + inva ----
        if (tid < 960) {
            const int g = tid >> 5 >= 20 ? 2 : (tid >> 5 >= 10 ? 1 : 0);
            const int slot = tid - g * 320;
            if (slot < TOT / 4) {
                if (g == 0) {
                    float4* u4 = (float4*)u;
                    float4 acc = u4[slot];
                    acc.x *= 0.5f; acc.y *= 0.5f; acc.z *= 0.5f; acc.w *= 0.5f;
                    accum9(acc, 0, slot, sel_p, sel_d);
                    u4[slot] = acc;
                } else if (g == 1) {
                    float4 acc = make_float4(0.f, 0.f, 0.f, 0.f);
                    accum9(acc, 9, slot, sel_p, sel_d);
                    ((float4*)uB)[slot] = acc;
                } else {
                    float4 acc = make_float4(0.f, 0.f, 0.f, 0.f);
                    accum9(acc, 18, slot, sel_p, sel_d);
                    ((float4*)uC)[slot] = acc;
                }
            }
        } else {
            float part = 0.0f;
            for (int p = tid - 960; p < TOT; p += 64) {
                float nv = ynew[p];
                float ps = fmaxf(0.5f * psi[p], nv);
                psi[p] = ps;
                phi[p] = fmaxf(0.5f * phi[p], nv);
                ynew[p] = 0.0f;
                part += ps;
            }
#pragma unroll
            for (int o = 16; o; o >>= 1) part += __shfl_xor_sync(0xffffffffu, part, o);
            if (lane == 0) red_alpha[(tid >> 5) - 30] = part;
            NAMED_BAR(2, 64);                              // NB2: alpha partials within warps 30-31
            if (tid == 960) {
                float a = red_alpha[0] + red_alpha[1];
                if (a == 0.0f) a = 1.0f;
                s_invalpha = 1.0f / a;
            }
        }
        __syncthreads();                                   // S5 (full) — publishes u/uB/uC, psi, phi, inva
    }

    // final carry outputs: x_b = psi/alpha, phi, psi
    const float inva = s_invalpha;
    for (int p = tid; p < TOT; p += T) {
        tail[p]            = psi[p] * inva;
        tail[TOT + p]      = phi[p];
        tail[2 * TOT + p]  = psi[p];
    }
}

// ---------------- launch ----------------
extern "C" void kernel_launch(void* const* d_in, const int* in_sizes, int n_in,
                              void* d_out, int out_size)
{
    const float* batch_x = (const float*)d_in[0];   // (B, 784)
    const float* Wa      = (const float*)d_in[1];   // (200, 784)
    const float* ba      = (const float*)d_in[2];   // (200,)
    const float* Wb      = (const float*)d_in[3];   // (1200, 1200)
    const float* bb      = (const float*)d_in[4];   // (1200,)
    const float* Wd      = (const float*)d_in[5];   // (784, 200)
    const float* bd      = (const float*)d_in[6];   // (784,)
    float* out = (float*)d_out;

    const int B = in_sizes[0] / DIN;

    float *pZA = nullptr, *pYmax = nullptr;
    cudaGetSymbolAddress((void**)&pZA, g_ZA);
    cudaGetSymbolAddress((void**)&pYmax, g_Ymax);

    // 1) Wb transpose for coalesced column gathers
    {
        dim3 tb(32, 8);
        dim3 tg((TOT + 31) / 32, (TOT + 31) / 32);
        transpose_wb<<<tg, tb>>>(Wb);
    }
    // 2) hoisted input GEMM: ZA[t][i] = Wa[i,:] . x_t + ba[i]
    {
        dim3 grid((B + 63) / 64, (MROWS + 63) / 64);
        gemm_abt_kernel<<<grid, 256>>>(batch_x, Wa, ba, pZA, B, MROWS, DIN);
    }
    // 3) sequential scan (records Ymax, writes carry tail)
    scan_kernel<<<1, 1024>>>(bb, out + (size_t)B * DIN, B);
    // 4) deferred output GEMM: preds[t][d] = Wd[d,:] . ymax_t + bd[d]
    {
        dim3 grid((B + 63) / 64, (DIN + 63) / 64);
        gemm_abt_kernel<<<grid, 256>>>(pYmax, Wd, bd, out, B, DIN, MROWS);
    }
}